// round 4
// baseline (speedup 1.0000x reference)
#include <cuda_runtime.h>
#include <cstdint>

#define S_LEN 2048
#define BATCH 32
#define HID   256
#define NCOL  1024   // 4*H
#define HPAD  68     // padded stride per 64-float k-block (bank decorrelation)

// 256 MB scratch for Zx = x @ Wx + b, layout [s][b][j]
__device__ float g_zx[(size_t)S_LEN * BATCH * NCOL];

// ----------------------------- helpers -----------------------------
__device__ __forceinline__ void fma2(unsigned long long &d, unsigned long long a, unsigned long long b) {
    asm("fma.rn.f32x2 %0, %1, %2, %0;" : "+l"(d) : "l"(a), "l"(b));
}
__device__ __forceinline__ unsigned long long pack2(float lo, float hi) {
    unsigned long long r; asm("mov.b64 %0, {%1, %2};" : "=l"(r) : "f"(lo), "f"(hi)); return r;
}
__device__ __forceinline__ float lo32(unsigned long long v){ return __uint_as_float((unsigned)(v & 0xffffffffull)); }
__device__ __forceinline__ float hi32(unsigned long long v){ return __uint_as_float((unsigned)(v >> 32)); }
__device__ __forceinline__ unsigned smem_u32(const void* p){ return (unsigned)__cvta_generic_to_shared(p); }
__device__ __forceinline__ unsigned mapa_rank(unsigned a, unsigned rk){
    unsigned r; asm("mapa.shared::cluster.u32 %0, %1, %2;" : "=r"(r) : "r"(a), "r"(rk)); return r;
}
__device__ __forceinline__ void st_cluster(unsigned a, float v){
    asm volatile("st.shared::cluster.f32 [%0], %1;" :: "r"(a), "f"(v) : "memory");
}
__device__ __forceinline__ void cluster_sync_(){
    asm volatile("barrier.cluster.arrive.aligned;" ::: "memory");
    asm volatile("barrier.cluster.wait.aligned;" ::: "memory");
}
__device__ __forceinline__ float tanha(float x){
    float y; asm("tanh.approx.f32 %0, %1;" : "=f"(y) : "f"(x)); return y;
}
__device__ __forceinline__ float sig(float x){ return fmaf(0.5f, tanha(0.5f * x), 0.5f); }

// ----------------------------- phase 1: Zx = x @ Wx + b (+ tail zeroing) -----------------------------
// M = 65536 (row r = s*32 + b), N = 1024, K = 256. 128x128 tile, 8x8 microtile.
__global__ void __launch_bounds__(256, 2)
gemm_x_kernel(const float* __restrict__ x, const float* __restrict__ W, const float* __restrict__ bias,
              float* __restrict__ out, long long tail_start, long long tail_n)
{
    __shared__ float As[32][128];   // [k][row]
    __shared__ float Bs[32][128];   // [k][col]

    const int tid = threadIdx.x;

    // fold the two trailing zero-tensors into the first 64 y-blocks of column-tile 0
    if (blockIdx.x == 0 && blockIdx.y < 64) {
        long long i = (long long)blockIdx.y * 256 + tid;
        if (i < tail_n) out[tail_start + i] = 0.0f;
    }

    const int colTile = blockIdx.x * 128;
    const int rowTile = blockIdx.y * 128;
    const int tx = tid & 15, ty = tid >> 4;

    float acc[8][8];
    #pragma unroll
    for (int i = 0; i < 8; i++)
        #pragma unroll
        for (int j = 0; j < 8; j++) acc[i][j] = 0.0f;

    const int arow = tid >> 3;          // 0..31
    const int akk  = (tid & 7) * 4;     // 0..28
    const int bkk  = tid >> 3;          // 0..31
    const int bj   = (tid & 7) * 16;    // 0..112

    for (int k0 = 0; k0 < 256; k0 += 32) {
        #pragma unroll
        for (int wv = 0; wv < 4; wv++) {
            int row = arow + wv * 32;
            int rr  = rowTile + row;
            int bb  = rr & 31;          // batch
            int ss  = rr >> 5;          // seq pos
            float4 v = *(const float4*)&x[((size_t)bb * S_LEN + ss) * 256 + k0 + akk];
            As[akk + 0][row] = v.x; As[akk + 1][row] = v.y;
            As[akk + 2][row] = v.z; As[akk + 3][row] = v.w;
        }
        #pragma unroll
        for (int wv = 0; wv < 4; wv++) {
            float4 v = *(const float4*)&W[(size_t)(k0 + bkk) * NCOL + colTile + bj + wv * 4];
            *(float4*)&Bs[bkk][bj + wv * 4] = v;
        }
        __syncthreads();

        #pragma unroll
        for (int kk = 0; kk < 32; kk++) {
            float a[8], b8[8];
            *(float4*)&a[0]  = *(const float4*)&As[kk][ty * 8];
            *(float4*)&a[4]  = *(const float4*)&As[kk][ty * 8 + 4];
            *(float4*)&b8[0] = *(const float4*)&Bs[kk][tx * 8];
            *(float4*)&b8[4] = *(const float4*)&Bs[kk][tx * 8 + 4];
            #pragma unroll
            for (int i = 0; i < 8; i++)
                #pragma unroll
                for (int j = 0; j < 8; j++)
                    acc[i][j] = fmaf(a[i], b8[j], acc[i][j]);
        }
        __syncthreads();
    }

    float bv[8];
    #pragma unroll
    for (int j = 0; j < 8; j++) bv[j] = bias[colTile + tx * 8 + j];

    #pragma unroll
    for (int i = 0; i < 8; i++) {
        size_t rr = (size_t)rowTile + ty * 8 + i;
        float4 o0, o1;
        o0.x = acc[i][0] + bv[0]; o0.y = acc[i][1] + bv[1];
        o0.z = acc[i][2] + bv[2]; o0.w = acc[i][3] + bv[3];
        o1.x = acc[i][4] + bv[4]; o1.y = acc[i][5] + bv[5];
        o1.z = acc[i][6] + bv[6]; o1.w = acc[i][7] + bv[7];
        *(float4*)&g_zx[rr * NCOL + colTile + tx * 8]     = o0;
        *(float4*)&g_zx[rr * NCOL + colTile + tx * 8 + 4] = o1;
    }
}

// ----------------------------- phase 2: the recurrence -----------------------------
// 16 clusters x 8 CTAs. Cluster p owns chains 2p, 2p+1. CTA rank r owns h-indices
// [r*32, r*32+32) and the 128 z-columns {gate*256 + r*32 + m}.
// Thread t: col c = t>>2 (0..127), k-quarter kq = t&3. Weights (col c, 64 k) live
// in 32 packed f32x2 registers, shared across both chains. k-reduction is 2
// shfl.bfly steps (kq lives in lane bits 0..1). h is cluster-replicated in SMEM
// (double-buffered by parity, padded kq-blocks for conflict-free broadcast LDS);
// the 64 h-owner threads broadcast via st.shared::cluster; one cluster.sync/step.
__global__ void __cluster_dims__(8, 1, 1) __launch_bounds__(512, 1)
lstm_chain_kernel(const float* __restrict__ W, const float* __restrict__ h0,
                  const float* __restrict__ c0, float* __restrict__ out)
{
    __shared__ __align__(16) float h_buf[2][2][4][HPAD];  // [parity][chain][kq][64(+pad)]
    __shared__ float zsm[2][128];                         // [chain][col]

    const int tid = threadIdx.x;
    const int p = blockIdx.x >> 3;     // chain-pair id 0..15
    const int r = blockIdx.x & 7;      // cluster rank 0..7

    const int c  = tid >> 2;           // col 0..127
    const int kq = tid & 3;            // k quarter (lane bits 0..1)
    const int g  = c >> 5;             // gate 0..3
    const int m  = c & 31;
    const int j  = g * 256 + r * 32 + m;

    // preload weights: 32 packed pairs over k in [kq*64, kq*64+64)
    unsigned long long w[32];
    {
        const float* Wh = W + (size_t)(256 + kq * 64) * NCOL + j;
        #pragma unroll
        for (int q = 0; q < 32; q++)
            w[q] = pack2(Wh[(size_t)(2 * q) * NCOL], Wh[(size_t)(2 * q + 1) * NCOL]);
    }

    // init h_buf[0] (full h for both chains, local copy per CTA)
    {
        int ch = tid >> 8, k = tid & 255;
        h_buf[0][ch][k >> 6][k & 63] = h0[(size_t)(2 * p + ch) * HID + k];
    }
    const int oc = tid >> 5, om = tid & 31;   // cell-state owners (tid<64)
    float cst = 0.0f;
    if (tid < 64) cst = c0[(size_t)(2 * p + oc) * HID + r * 32 + om];

    const float* zx0 = g_zx + (size_t)(2 * p) * NCOL + j;   // chain 0, this col
    const float* zx1 = zx0 + NCOL;                          // chain 1

    __syncthreads();
    cluster_sync_();   // all CTAs alive + h_buf[0] init done before DSMEM use

    for (int s = 0; s < S_LEN; s++) {
        const int par = s & 1;

        // issue zx loads early; latency hidden under the FMA block
        float x0 = 0.f, x1 = 0.f;
        if (kq == 0) {
            size_t off = (size_t)s * (BATCH * NCOL);
            x0 = __ldg(zx0 + off);
            x1 = __ldg(zx1 + off);
        }

        // Wh . h for both chains over this thread's 64-k quarter (f32x2 SIMD)
        unsigned long long a0 = 0ull, a1 = 0ull;
        const ulonglong2* hb0 = (const ulonglong2*)&h_buf[par][0][kq][0];
        const ulonglong2* hb1 = (const ulonglong2*)&h_buf[par][1][kq][0];
        #pragma unroll
        for (int i = 0; i < 16; i++) {
            ulonglong2 p0 = hb0[i];
            ulonglong2 p1 = hb1[i];
            fma2(a0, w[2 * i],     p0.x);
            fma2(a0, w[2 * i + 1], p0.y);
            fma2(a1, w[2 * i],     p1.x);
            fma2(a1, w[2 * i + 1], p1.y);
        }
        float s0 = lo32(a0) + hi32(a0);
        float s1 = lo32(a1) + hi32(a1);
        // reduce the 4 k-quarters (lane bits 0..1)
        s0 += __shfl_xor_sync(0xffffffffu, s0, 1);
        s0 += __shfl_xor_sync(0xffffffffu, s0, 2);
        s1 += __shfl_xor_sync(0xffffffffu, s1, 1);
        s1 += __shfl_xor_sync(0xffffffffu, s1, 2);

        if (kq == 0) {
            zsm[0][c] = tanha(s0 + x0);
            zsm[1][c] = tanha(s1 + x1);
        }
        __syncthreads();

        if (tid < 64) {
            float iv = sig(zsm[oc][om]);
            float fv = sig(zsm[oc][32 + om]);
            float gv = tanha(zsm[oc][64 + om]);
            float ov = sig(zsm[oc][96 + om]);
            cst = fv * cst + iv * gv;
            float hn = tanha(cst) * ov;
            out[((size_t)(2 * p + oc) * S_LEN + s) * HID + r * 32 + om] = hn;
            // broadcast new h to every CTA in the cluster (incl. self)
            unsigned la = smem_u32(&h_buf[par ^ 1][oc][r >> 1][(r & 1) * 32 + om]);
            #pragma unroll
            for (int rk = 0; rk < 8; rk++) st_cluster(mapa_rank(la, rk), hn);
        }
        cluster_sync_();  // release stores / acquire for next step
    }
}

// ----------------------------- launcher -----------------------------
extern "C" void kernel_launch(void* const* d_in, const int* in_sizes, int n_in,
                              void* d_out, int out_size) {
    const float* x    = (const float*)d_in[0];   // (32, 2048, 256)
    const float* h0   = (const float*)d_in[1];   // (1, 32, 256)
    const float* c0   = (const float*)d_in[2];   // (1, 32, 256)
    const float* W    = (const float*)d_in[3];   // (512, 1024)
    const float* bias = (const float*)d_in[4];   // (1024,)
    float* out = (float*)d_out;

    const long long main_elems = (long long)BATCH * S_LEN * HID;  // 16,777,216
    const long long tail = (long long)out_size - main_elems;      // two zero tensors

    gemm_x_kernel<<<dim3(8, 512, 1), 256>>>(x, W, bias, out, main_elems, tail > 0 ? tail : 0);
    lstm_chain_kernel<<<128, 512>>>(W, h0, c0, out);
}

// round 7
// speedup vs baseline: 1.3083x; 1.3083x over previous
#include <cuda_runtime.h>
#include <cstdint>

#define S_LEN 2048
#define BATCH 32
#define HID   256
#define NCOL  1024   // 4*H
#define HROW  320    // 256 + 4-float pad per 16 floats

// 256 MB scratch for Zx = x @ Wx + b, layout [s][b][j]
__device__ float g_zx[(size_t)S_LEN * BATCH * NCOL];

// ----------------------------- helpers -----------------------------
__device__ __forceinline__ void fma2(unsigned long long &d, unsigned long long a, unsigned long long b) {
    asm("fma.rn.f32x2 %0, %1, %2, %0;" : "+l"(d) : "l"(a), "l"(b));
}
__device__ __forceinline__ unsigned long long pack2(float lo, float hi) {
    unsigned long long r; asm("mov.b64 %0, {%1, %2};" : "=l"(r) : "f"(lo), "f"(hi)); return r;
}
__device__ __forceinline__ float lo32(unsigned long long v){ return __uint_as_float((unsigned)(v & 0xffffffffull)); }
__device__ __forceinline__ float hi32(unsigned long long v){ return __uint_as_float((unsigned)(v >> 32)); }
__device__ __forceinline__ unsigned smem_u32(const void* p){ return (unsigned)__cvta_generic_to_shared(p); }
__device__ __forceinline__ unsigned mapa_rank(unsigned a, unsigned rk){
    unsigned r; asm("mapa.shared::cluster.u32 %0, %1, %2;" : "=r"(r) : "r"(a), "r"(rk)); return r;
}
__device__ __forceinline__ void cluster_sync_(){
    asm volatile("barrier.cluster.arrive.aligned;" ::: "memory");
    asm volatile("barrier.cluster.wait.aligned;" ::: "memory");
}
__device__ __forceinline__ float tanha(float x){
    float y; asm("tanh.approx.f32 %0, %1;" : "=f"(y) : "f"(x)); return y;
}
__device__ __forceinline__ float sig(float x){ return fmaf(0.5f, tanha(0.5f * x), 0.5f); }

__device__ __forceinline__ void mbar_init(unsigned bar, unsigned cnt){
    asm volatile("mbarrier.init.shared.b64 [%0], %1;" :: "r"(bar), "r"(cnt) : "memory");
}
__device__ __forceinline__ void mbar_arm(unsigned bar, unsigned tx){
    asm volatile("mbarrier.arrive.expect_tx.shared.b64 _, [%0], %1;" :: "r"(bar), "r"(tx) : "memory");
}
__device__ __forceinline__ void mbar_wait(unsigned bar, unsigned parity){
    asm volatile(
        "{\n\t.reg .pred P;\n\t"
        "WL_%=:\n\t"
        "mbarrier.try_wait.parity.acquire.cluster.shared::cta.b64 P, [%0], %1, 0x989680;\n\t"
        "@!P bra WL_%=;\n\t}"
        :: "r"(bar), "r"(parity) : "memory");
}
// remote store + remote mbarrier tx-completion in one instruction
__device__ __forceinline__ void st_async_f32(unsigned raddr, unsigned rbar, float v){
    asm volatile("st.async.shared::cluster.mbarrier::complete_tx::bytes.b32 [%0], %1, [%2];"
                 :: "r"(raddr), "f"(v), "r"(rbar) : "memory");
}

// ----------------------------- phase 1: Zx = x @ Wx + b (+ tail zeroing) -----------------------------
__global__ void __launch_bounds__(256, 2)
gemm_x_kernel(const float* __restrict__ x, const float* __restrict__ W, const float* __restrict__ bias,
              float* __restrict__ out, long long tail_start, long long tail_n)
{
    __shared__ float As[32][128];
    __shared__ float Bs[32][128];

    const int tid = threadIdx.x;

    if (blockIdx.x == 0 && blockIdx.y < 64) {
        long long i = (long long)blockIdx.y * 256 + tid;
        if (i < tail_n) out[tail_start + i] = 0.0f;
    }

    const int colTile = blockIdx.x * 128;
    const int rowTile = blockIdx.y * 128;
    const int tx = tid & 15, ty = tid >> 4;

    float acc[8][8];
    #pragma unroll
    for (int i = 0; i < 8; i++)
        #pragma unroll
        for (int j = 0; j < 8; j++) acc[i][j] = 0.0f;

    const int arow = tid >> 3;
    const int akk  = (tid & 7) * 4;
    const int bkk  = tid >> 3;
    const int bj   = (tid & 7) * 16;

    for (int k0 = 0; k0 < 256; k0 += 32) {
        #pragma unroll
        for (int wv = 0; wv < 4; wv++) {
            int row = arow + wv * 32;
            int rr  = rowTile + row;
            int bb  = rr & 31;
            int ss  = rr >> 5;
            float4 v = *(const float4*)&x[((size_t)bb * S_LEN + ss) * 256 + k0 + akk];
            As[akk + 0][row] = v.x; As[akk + 1][row] = v.y;
            As[akk + 2][row] = v.z; As[akk + 3][row] = v.w;
        }
        #pragma unroll
        for (int wv = 0; wv < 4; wv++) {
            float4 v = *(const float4*)&W[(size_t)(k0 + bkk) * NCOL + colTile + bj + wv * 4];
            *(float4*)&Bs[bkk][bj + wv * 4] = v;
        }
        __syncthreads();

        #pragma unroll
        for (int kk = 0; kk < 32; kk++) {
            float a[8], b8[8];
            *(float4*)&a[0]  = *(const float4*)&As[kk][ty * 8];
            *(float4*)&a[4]  = *(const float4*)&As[kk][ty * 8 + 4];
            *(float4*)&b8[0] = *(const float4*)&Bs[kk][tx * 8];
            *(float4*)&b8[4] = *(const float4*)&Bs[kk][tx * 8 + 4];
            #pragma unroll
            for (int i = 0; i < 8; i++)
                #pragma unroll
                for (int j = 0; j < 8; j++)
                    acc[i][j] = fmaf(a[i], b8[j], acc[i][j]);
        }
        __syncthreads();
    }

    float bv[8];
    #pragma unroll
    for (int j = 0; j < 8; j++) bv[j] = bias[colTile + tx * 8 + j];

    #pragma unroll
    for (int i = 0; i < 8; i++) {
        size_t rr = (size_t)rowTile + ty * 8 + i;
        float4 o0, o1;
        o0.x = acc[i][0] + bv[0]; o0.y = acc[i][1] + bv[1];
        o0.z = acc[i][2] + bv[2]; o0.w = acc[i][3] + bv[3];
        o1.x = acc[i][4] + bv[4]; o1.y = acc[i][5] + bv[5];
        o1.z = acc[i][6] + bv[6]; o1.w = acc[i][7] + bv[7];
        *(float4*)&g_zx[rr * NCOL + colTile + tx * 8]     = o0;
        *(float4*)&g_zx[rr * NCOL + colTile + tx * 8 + 4] = o1;
    }
}

// ----------------------------- phase 2: the recurrence -----------------------------
// 16 clusters x 8 CTAs, cluster p owns chains 2p, 2p+1. CTA rank r owns hidden
// units [r*32, r*32+32). Thread t = m*16 + ks: hidden unit m (local), k-slice
// ks (16 k each), ALL 4 gates, both chains. Weights: 4 gates x 16 k = 32 f32x2
// regs. Reduction over ks = 4 shfl.bfly (ks = lane bits 0..3). ks==0 lanes then
// compute gates/c/h in-register and push h to all 8 CTAs via st.async with
// remote mbarrier tx-completion. Ping-pong mbarriers; no cluster.sync in the
// steady-state loop. Final step sends nothing; one cluster.sync before exit.
__global__ void __cluster_dims__(8, 1, 1) __launch_bounds__(512, 1)
lstm_chain_kernel(const float* __restrict__ W, const float* __restrict__ h0,
                  const float* __restrict__ c0, float* __restrict__ out)
{
    __shared__ __align__(16) float h_buf[2][2][HROW];   // [parity][chain][padded k]
    __shared__ __align__(8) unsigned long long mbar[2];

    const int tid = threadIdx.x;
    const int p = blockIdx.x >> 3;
    const int r = blockIdx.x & 7;

    const int m  = tid >> 4;     // 0..31 hidden unit (local)
    const int ks = tid & 15;     // k-slice

    // ---- weights: w2[g*8+q] covers k = ks*16 + 2q, 2q+1, col = g*256 + r*32 + m
    unsigned long long w2[32];
    {
        const float* Wb = W + (size_t)(256 + ks * 16) * NCOL + r * 32 + m;
        #pragma unroll
        for (int g = 0; g < 4; g++)
            #pragma unroll
            for (int q = 0; q < 8; q++)
                w2[g * 8 + q] = pack2(Wb[(size_t)(2 * q) * NCOL + g * 256],
                                      Wb[(size_t)(2 * q + 1) * NCOL + g * 256]);
    }

    // ---- barrier init + pre-arm
    const unsigned hb_base = smem_u32(&h_buf[0][0][0]);
    const unsigned mb_base = smem_u32(&mbar[0]);
    const int dMB = (int)(mb_base - hb_base);
    if (tid == 511) {
        mbar_init(mb_base, 1);
        mbar_init(mb_base + 8, 1);
        mbar_arm(mb_base, 2048);      // receives step-1 stores, waited step 2
        mbar_arm(mb_base + 8, 2048);  // receives step-0 stores, waited step 1
    }

    // ---- init h_buf[0] (padded layout: +4 floats per 16)
    {
        int ch = tid >> 8, k = tid & 255;
        h_buf[0][ch][k + ((k >> 4) << 2)] = h0[(size_t)(2 * p + ch) * HID + k];
    }

    // ---- cell state (owners: ks == 0)
    float cst0 = 0.f, cst1 = 0.f;
    if (ks == 0) {
        cst0 = c0[(size_t)(2 * p)     * HID + r * 32 + m];
        cst1 = c0[(size_t)(2 * p + 1) * HID + r * 32 + m];
    }

    // ---- remote store bases (rank-mapped h_buf base; peer mbar = +dMB)
    unsigned hmap[8];
    #pragma unroll
    for (int rk = 0; rk < 8; rk++) hmap[rk] = mapa_rank(hb_base, rk);

    const int kg = r * 32 + m;
    const int po = kg + ((kg >> 4) << 2);   // padded offset of this unit

    const float* zx_base = g_zx + (size_t)(2 * p) * NCOL + r * 32 + m;
    float* out_base = out + ((size_t)(2 * p) * S_LEN) * HID + r * 32 + m;

    __syncthreads();
    cluster_sync_();   // barriers init'd + h_buf[0] ready cluster-wide

    int ph0 = 0, ph1 = 0;

    for (int s = 0; s < S_LEN; s++) {
        const int par = s & 1;

        // zx loads first — independent of peers, latency hides under the wait+FMA
        float zxv[8];
        if (ks == 0) {
            const float* zp = zx_base + (size_t)s * (BATCH * NCOL);
            #pragma unroll
            for (int g = 0; g < 4; g++) {
                zxv[g]     = __ldg(zp + g * 256);
                zxv[4 + g] = __ldg(zp + NCOL + g * 256);
            }
        }

        if (s > 0) {
            unsigned bar = mb_base + (unsigned)par * 8;
            int ph = par ? ph1 : ph0;
            mbar_wait(bar, (unsigned)ph);
            if (par) ph1 ^= 1; else ph0 ^= 1;
            if (tid == 511) mbar_arm(bar, 2048);   // re-arm for step s+2
        }

        // ---- Wh . h over this thread's 16-k slice, 4 gates, 2 chains
        unsigned long long accA[4] = {0,0,0,0}, accB[4] = {0,0,0,0};
        {
            const ulonglong2* hb = (const ulonglong2*)&h_buf[par][0][ks * 20];
            ulonglong2 q0 = hb[0], q1 = hb[1], q2 = hb[2], q3 = hb[3];
            unsigned long long h8[8] = {q0.x, q0.y, q1.x, q1.y, q2.x, q2.y, q3.x, q3.y};
            #pragma unroll
            for (int g = 0; g < 4; g++)
                #pragma unroll
                for (int q = 0; q < 8; q++) fma2(accA[g], w2[g * 8 + q], h8[q]);
        }
        {
            const ulonglong2* hb = (const ulonglong2*)&h_buf[par][1][ks * 20];
            ulonglong2 q0 = hb[0], q1 = hb[1], q2 = hb[2], q3 = hb[3];
            unsigned long long h8[8] = {q0.x, q0.y, q1.x, q1.y, q2.x, q2.y, q3.x, q3.y};
            #pragma unroll
            for (int g = 0; g < 4; g++)
                #pragma unroll
                for (int q = 0; q < 8; q++) fma2(accB[g], w2[g * 8 + q], h8[q]);
        }

        float sv[8];
        #pragma unroll
        for (int g = 0; g < 4; g++) {
            sv[g]     = lo32(accA[g]) + hi32(accA[g]);
            sv[4 + g] = lo32(accB[g]) + hi32(accB[g]);
        }
        // reduce the 16 k-slices (ks = lane bits 0..3)
        #pragma unroll
        for (int v = 0; v < 8; v++) {
            sv[v] += __shfl_xor_sync(0xffffffffu, sv[v], 1);
            sv[v] += __shfl_xor_sync(0xffffffffu, sv[v], 2);
            sv[v] += __shfl_xor_sync(0xffffffffu, sv[v], 4);
            sv[v] += __shfl_xor_sync(0xffffffffu, sv[v], 8);
        }

        if (ks == 0) {
            // chain 0
            float zi = tanha(sv[0] + zxv[0]);
            float zf = tanha(sv[1] + zxv[1]);
            float zg = tanha(sv[2] + zxv[2]);
            float zo = tanha(sv[3] + zxv[3]);
            cst0 = sig(zf) * cst0 + sig(zi) * tanha(zg);
            float hn0 = tanha(cst0) * sig(zo);
            // chain 1
            zi = tanha(sv[4] + zxv[4]);
            zf = tanha(sv[5] + zxv[5]);
            zg = tanha(sv[6] + zxv[6]);
            zo = tanha(sv[7] + zxv[7]);
            cst1 = sig(zf) * cst1 + sig(zi) * tanha(zg);
            float hn1 = tanha(cst1) * sig(zo);

            out_base[(size_t)s * HID]           = hn0;
            out_base[((size_t)S_LEN + s) * HID] = hn1;

            if (s + 1 < S_LEN) {
                const int parN = par ^ 1;
                const unsigned off0 = (unsigned)(((parN * 2 + 0) * HROW + po) * 4);
                const unsigned off1 = (unsigned)(((parN * 2 + 1) * HROW + po) * 4);
                const unsigned mbo  = (unsigned)(dMB + parN * 8);
                #pragma unroll
                for (int rk = 0; rk < 8; rk++) {
                    st_async_f32(hmap[rk] + off0, hmap[rk] + mbo, hn0);
                    st_async_f32(hmap[rk] + off1, hmap[rk] + mbo, hn1);
                }
            }
        }
    }

    // no CTA may exit while peers could still have remote stores in flight
    cluster_sync_();
}

// ----------------------------- launcher -----------------------------
extern "C" void kernel_launch(void* const* d_in, const int* in_sizes, int n_in,
                              void* d_out, int out_size) {
    const float* x    = (const float*)d_in[0];   // (32, 2048, 256)
    const float* h0   = (const float*)d_in[1];   // (1, 32, 256)
    const float* c0   = (const float*)d_in[2];   // (1, 32, 256)
    const float* W    = (const float*)d_in[3];   // (512, 1024)
    const float* bias = (const float*)d_in[4];   // (1024,)
    float* out = (float*)d_out;

    const long long main_elems = (long long)BATCH * S_LEN * HID;
    const long long tail = (long long)out_size - main_elems;

    gemm_x_kernel<<<dim3(8, 512, 1), 256>>>(x, W, bias, out, main_elems, tail > 0 ? tail : 0);
    lstm_chain_kernel<<<128, 512>>>(W, h0, c0, out);
}